// round 17
// baseline (speedup 1.0000x reference)
#include <cuda_runtime.h>

#define K     3
#define K2    9
#define PAD   1
#define Bn    2
#define Hn    352
#define Wn    1216
#define HW    (Hn * Wn)

#define TX    64
#define TY    8
#define HALO  8
#define TW    (TX + 2 * HALO)      // 80
#define TH    (TY + 2 * HALO)      // 24
#define TS    81                   // odd row stride (bank spread)

// Block (64,8) = 512 threads, 1 px/thread. Depth gathers come from a zero-padded
// smem tile (LDS, smem crossbar) instead of scatter LDGs (l1tex wavefronts).
// Escapes beyond the halo are handled by FLAT per-lane predicated global loads
// (no branches; predicated-off LDGs produce no memory traffic).
__global__ __launch_bounds__(TX * TY, 2)
void postproc_deconv_kernel(const float* __restrict__ depth,
                            const float* __restrict__ weight,
                            const float* __restrict__ offset,
                            const float* __restrict__ wker,
                            const float* __restrict__ bias,
                            float* __restrict__ out) {
    __shared__ float tile[TH * TS];

    int tx  = threadIdx.x;              // 0..63
    int ty  = threadIdx.y;              // 0..7
    int tid = ty * TX + tx;
    int bx0 = blockIdx.x * TX;
    int by0 = blockIdx.y * TY;
    int b   = blockIdx.z;

    const float* dplane = depth + b * HW;
    int ox = bx0 - HALO;
    int oy = by0 - HALO;

    // ---- cooperative zero-padded depth tile load (1920 elems, 512 thr) ----
    #pragma unroll
    for (int i = tid; i < TH * TW; i += TX * TY) {
        int r = i / TW;
        int c = i - r * TW;
        int gy = oy + r;
        int gx = ox + c;
        float v = 0.f;
        if (((unsigned)gy < Hn) & ((unsigned)gx < Wn))
            v = __ldg(dplane + gy * Wn + gx);
        tile[r * TS + c] = v;
    }

    int x   = bx0 + tx;
    int y   = by0 + ty;
    int pix = y * Wn + x;
    const float* wbase = weight + b * (K2 * HW) + pix;
    const float* obase = offset + b * (2 * K2 * HW) + pix;

    // ---- front-batch ALL 18 offset loads (overlaps with tile load + sync) ----
    float dyv[K2], dxv[K2];
    #pragma unroll
    for (int k = 0; k < K2; k++) {
        dyv[k] = __ldg(obase + (2 * k)     * HW);
        dxv[k] = __ldg(obase + (2 * k + 1) * HW);
    }

    __syncthreads();

    // Fused: out = d + A - (ws/9)*S + bias
    float A = 0.f, S = 0.f, ws = 0.f;

    #pragma unroll
    for (int k = 0; k < K2; k++) {
        int kh = k / K;
        int kw = k % K;
        float wk = __ldg(wbase + k * HW);
        float wc = __ldg(wker + k);            // uniform broadcast, L1-hit

        float py = (float)(y - PAD + kh) + dyv[k];
        float px = (float)(x - PAD + kw) + dxv[k];
        float y0f = floorf(py);
        float x0f = floorf(px);
        float ly = py - y0f;
        float lx = px - x0f;
        int y0 = (int)y0f;
        int x0 = (int)x0f;

        int sy = y0 - oy;                      // tile-relative
        int sx = x0 - ox;

        // 2x2 footprint fully inside tile?
        bool esc = ((unsigned)sy > (unsigned)(TH - 2)) |
                   ((unsigned)sx > (unsigned)(TW - 2));

        // Clamped LDS (always smem-safe); values only used when !esc.
        int syc = min(max(sy, 0), TH - 2);
        int sxc = min(max(sx, 0), TW - 2);
        const float* p = &tile[syc * TS + sxc];
        float v00 = p[0];
        float v01 = p[1];
        float v10 = p[TS];
        float v11 = p[TS + 1];

        // Flat predicated rescue for escaped lanes (no branches).
        if (esc) { v00 = 0.f; v01 = 0.f; v10 = 0.f; v11 = 0.f; }
        {
            bool yv0 = esc & ((unsigned)y0 < Hn);
            bool yv1 = esc & ((unsigned)(y0 + 1) < Hn);
            bool xv0 = (unsigned)x0 < Wn;
            bool xv1 = (unsigned)(x0 + 1) < Wn;
            int base0 = y0 * Wn;
            int base1 = base0 + Wn;
            if (yv0 & xv0) v00 = __ldg(dplane + base0 + x0);
            if (yv0 & xv1) v01 = __ldg(dplane + base0 + x0 + 1);
            if (yv1 & xv0) v10 = __ldg(dplane + base1 + x0);
            if (yv1 & xv1) v11 = __ldg(dplane + base1 + x0 + 1);
        }

        float omly = 1.f - ly;
        float omlx = 1.f - lx;
        float top = fmaf(omlx, v00, lx * v01);
        float bot = fmaf(omlx, v10, lx * v11);
        float s   = fmaf(omly, top, ly * bot);

        float t = wc * s;
        A  = fmaf(t, wk, A);
        S += t;
        ws += wk;
    }

    float d  = tile[(HALO + ty) * TS + (HALO + tx)];
    float bb = __ldg(bias);
    out[b * HW + pix] = d + A - (ws * (1.0f / 9.0f)) * S + bb;
}

extern "C" void kernel_launch(void* const* d_in, const int* in_sizes, int n_in,
                              void* d_out, int out_size) {
    const float* depth  = (const float*)d_in[0];
    const float* weight = (const float*)d_in[1];
    const float* offset = (const float*)d_in[2];
    const float* wker   = (const float*)d_in[3];
    const float* bias   = (const float*)d_in[4];
    float* out = (float*)d_out;

    dim3 block(TX, TY, 1);
    dim3 grid(Wn / TX, Hn / TY, Bn);       // 19 x 44 x 2
    postproc_deconv_kernel<<<grid, block>>>(depth, weight, offset, wker, bias, out);
}